// round 1
// baseline (speedup 1.0000x reference)
#include <cuda_runtime.h>

#define NN 50000
#define EE 1250000
#define DD 64
#define HH 64
#define GG 64

// Scratch (device globals; no allocation in kernel_launch)
__device__ float    g_xws[NN*HH];   // (h @ W) * dinv[row]   (scaled features)
__device__ float    g_agg[NN*HH];   // scatter accumulator
__device__ float    g_dinv[NN];
__device__ unsigned g_deg[NN];
__device__ float    g_cnt[GG];
__device__ float    g_sumP[GG];
__device__ int      g_idx64;        // 1 if indices are int64, else int32

// ---------------------------------------------------------------------------
// dtype detection: batch is sorted in [0,64). If stored as int64, the int32
// word at index NN-1 (odd) is a high word == 0. If int32, it's G-1 (w.h.p. >0).
__global__ void k_detect(const int* batch_raw) {
    g_idx64 = (batch_raw[NN - 1] == 0) ? 1 : 0;
}

__global__ void k_init() {
    int i = blockIdx.x * blockDim.x + threadIdx.x;
    if (i < NN) g_deg[i] = 0u;
    if (i < GG) { g_cnt[i] = 0.f; g_sumP[i] = 0.f; }
}

__device__ __forceinline__ int load_idx(const void* p, long long i, int is64) {
    return is64 ? (int)((const long long*)p)[i] : ((const int*)p)[i];
}

// degree (in-degree over dst) + per-graph node counts
__global__ void k_count(const void* ei, const void* batch) {
    int i = blockIdx.x * blockDim.x + threadIdx.x;
    int is64 = g_idx64;
    if (i < EE) {
        int d = load_idx(ei, (long long)EE + i, is64);
        atomicAdd(&g_deg[d], 1u);
    }
    if (i < NN) {
        int b = load_idx(batch, i, is64);
        atomicAdd(&g_cnt[b], 1.0f);
    }
}

__global__ void k_dinv() {
    int i = blockIdx.x * blockDim.x + threadIdx.x;
    if (i < NN) g_dinv[i] = rsqrtf((float)g_deg[i] + 1.0f);
}

// ---------------------------------------------------------------------------
// Fused GEMM: reads input (mode 0: raw x; mode 1: relu(dinv*(agg+xws)+bprev)),
// computes h@W, writes g_xws = out*dinv, zeroes g_agg for the next scatter.
// Block = 256 threads handles 32 rows x 64 cols. W transposed in smem for
// vectorized conflict-free LDS.128.
__global__ __launch_bounds__(256) void k_gemm(const float* __restrict__ X,
                                              const float* __restrict__ W,
                                              const float* __restrict__ bprev,
                                              int mode)
{
    __shared__ float sWt[64][68];   // Wt[j][k] = W[k][j], pad 68 -> conflict-free
    __shared__ float sIn[32][68];

    int t = threadIdx.x;
    int row0 = blockIdx.x * 32;

    // Load + transpose W (coalesced float4 reads, scalar smem writes)
    #pragma unroll
    for (int p = 0; p < 4; p++) {
        int off = p * 1024 + t * 4;
        float4 w = *(const float4*)(W + off);
        int k = off >> 6;
        int j = off & 63;
        sWt[j+0][k] = w.x; sWt[j+1][k] = w.y; sWt[j+2][k] = w.z; sWt[j+3][k] = w.w;
    }

    // Load input tile: thread -> row rr, 8 contiguous cols
    int rr = t >> 3;
    int c0 = (t & 7) * 8;
    int n  = row0 + rr;
    if (n < NN) {
        if (mode == 0) {
            float4 a = *(const float4*)(X + (long long)n*64 + c0);
            float4 b = *(const float4*)(X + (long long)n*64 + c0 + 4);
            *(float4*)&sIn[rr][c0]   = a;
            *(float4*)&sIn[rr][c0+4] = b;
        } else {
            float dv = g_dinv[n];
            float4 a1 = *(const float4*)(g_agg + (long long)n*64 + c0);
            float4 a2 = *(const float4*)(g_agg + (long long)n*64 + c0 + 4);
            float4 s1 = *(const float4*)(g_xws + (long long)n*64 + c0);
            float4 s2 = *(const float4*)(g_xws + (long long)n*64 + c0 + 4);
            float4 b1 = *(const float4*)(bprev + c0);
            float4 b2 = *(const float4*)(bprev + c0 + 4);
            float4 r1, r2;
            r1.x = fmaxf(fmaf(dv, a1.x + s1.x, b1.x), 0.f);
            r1.y = fmaxf(fmaf(dv, a1.y + s1.y, b1.y), 0.f);
            r1.z = fmaxf(fmaf(dv, a1.z + s1.z, b1.z), 0.f);
            r1.w = fmaxf(fmaf(dv, a1.w + s1.w, b1.w), 0.f);
            r2.x = fmaxf(fmaf(dv, a2.x + s2.x, b2.x), 0.f);
            r2.y = fmaxf(fmaf(dv, a2.y + s2.y, b2.y), 0.f);
            r2.z = fmaxf(fmaf(dv, a2.z + s2.z, b2.z), 0.f);
            r2.w = fmaxf(fmaf(dv, a2.w + s2.w, b2.w), 0.f);
            *(float4*)&sIn[rr][c0]   = r1;
            *(float4*)&sIn[rr][c0+4] = r2;
            // zero accumulator for this layer's scatter
            float4 z = make_float4(0.f, 0.f, 0.f, 0.f);
            *(float4*)(g_agg + (long long)n*64 + c0)     = z;
            *(float4*)(g_agg + (long long)n*64 + c0 + 4) = z;
        }
    } else {
        float4 z = make_float4(0.f, 0.f, 0.f, 0.f);
        *(float4*)&sIn[rr][c0]   = z;
        *(float4*)&sIn[rr][c0+4] = z;
    }
    __syncthreads();

    // Compute: warp w -> rows w*4..w*4+3; lane l -> cols l, l+32
    int wp = t >> 5, l = t & 31;
    int r0 = wp * 4;
    float acc[4][2] = {};
    #pragma unroll
    for (int k4 = 0; k4 < 64; k4 += 4) {
        float4 w0 = *(float4*)&sWt[l][k4];
        float4 w1 = *(float4*)&sWt[l + 32][k4];
        #pragma unroll
        for (int r = 0; r < 4; r++) {
            float4 a = *(float4*)&sIn[r0 + r][k4];
            acc[r][0] += a.x*w0.x + a.y*w0.y + a.z*w0.z + a.w*w0.w;
            acc[r][1] += a.x*w1.x + a.y*w1.y + a.z*w1.z + a.w*w1.w;
        }
    }

    #pragma unroll
    for (int r = 0; r < 4; r++) {
        int n2 = row0 + r0 + r;
        if (n2 < NN) {
            float dv = g_dinv[n2];
            g_xws[(long long)n2*64 + l]      = acc[r][0] * dv;
            g_xws[(long long)n2*64 + l + 32] = acc[r][1] * dv;
            if (mode == 0) {    // first layer: also initialize accumulator
                g_agg[(long long)n2*64 + l]      = 0.f;
                g_agg[(long long)n2*64 + l + 32] = 0.f;
            }
        }
    }
}

// ---------------------------------------------------------------------------
// Edge scatter: agg[dst] += xws[src]. Pure copy-reduce, vector RED (16B).
// 8 threads per edge, each moves 8 floats (2 x v4 red).
__global__ __launch_bounds__(256) void k_scatter(const void* __restrict__ ei) {
    long long idx = (long long)blockIdx.x * blockDim.x + threadIdx.x;
    int e = (int)(idx >> 3);
    if (e >= EE) return;
    int c = ((int)idx & 7) * 8;
    int is64 = g_idx64;
    int s, d;
    if (is64) {
        const long long* p = (const long long*)ei;
        s = (int)p[e]; d = (int)p[EE + e];
    } else {
        const int* p = (const int*)ei;
        s = p[e]; d = p[EE + e];
    }
    const float4* src = (const float4*)(g_xws + (long long)s*64 + c);
    float4 v0 = src[0];
    float4 v1 = src[1];
    float* dst = g_agg + (long long)d*64 + c;
    asm volatile("red.global.add.v4.f32 [%0], {%1,%2,%3,%4};"
                 :: "l"(dst), "f"(v0.x), "f"(v0.y), "f"(v0.z), "f"(v0.w) : "memory");
    asm volatile("red.global.add.v4.f32 [%0], {%1,%2,%3,%4};"
                 :: "l"(dst + 4), "f"(v1.x), "f"(v1.y), "f"(v1.z), "f"(v1.w) : "memory");
}

// ---------------------------------------------------------------------------
// Final-layer epilogue + mean-pool head: p[n] = <dinv*(agg+xws)+b2, Wp>,
// accumulate per-graph sums.
__global__ __launch_bounds__(256) void k_pool(const float* __restrict__ b2,
                                              const float* __restrict__ Wp,
                                              const void* __restrict__ batch)
{
    __shared__ float sWp[64];
    __shared__ float sB[64];
    int t = threadIdx.x;
    if (t < 64) { sWp[t] = Wp[t]; sB[t] = b2[t]; }
    __syncthreads();
    int n = blockIdx.x * blockDim.x + t;
    if (n >= NN) return;
    float dv = g_dinv[n];
    const float4* A = (const float4*)(g_agg + (long long)n*64);
    const float4* S = (const float4*)(g_xws + (long long)n*64);
    float p = 0.f;
    #pragma unroll
    for (int k4 = 0; k4 < 16; k4++) {
        float4 a = A[k4], s = S[k4];
        float4 w = *(const float4*)&sWp[k4*4];
        float4 b = *(const float4*)&sB[k4*4];
        p += (fmaf(dv, a.x + s.x, b.x)) * w.x;
        p += (fmaf(dv, a.y + s.y, b.y)) * w.y;
        p += (fmaf(dv, a.z + s.z, b.z)) * w.z;
        p += (fmaf(dv, a.w + s.w, b.w)) * w.w;
    }
    int g = g_idx64 ? (int)((const long long*)batch)[n] : ((const int*)batch)[n];
    atomicAdd(&g_sumP[g], p);
}

__global__ void k_final(const float* __restrict__ bp, float* __restrict__ out) {
    int g = threadIdx.x;
    if (g < GG) out[g] = g_sumP[g] / fmaxf(g_cnt[g], 1.0f) + bp[0];
}

// ---------------------------------------------------------------------------
extern "C" void kernel_launch(void* const* d_in, const int* in_sizes, int n_in,
                              void* d_out, int out_size)
{
    const float* x     = (const float*)d_in[0];
    const void*  ei    = d_in[1];
    const void*  batch = d_in[2];
    const float* W0    = (const float*)d_in[3];
    const float* b0    = (const float*)d_in[4];
    const float* W1    = (const float*)d_in[5];
    const float* b1    = (const float*)d_in[6];
    const float* W2    = (const float*)d_in[7];
    const float* b2    = (const float*)d_in[8];
    const float* Wp    = (const float*)d_in[9];
    const float* bp    = (const float*)d_in[10];
    float* out = (float*)d_out;

    k_detect<<<1, 1>>>((const int*)batch);
    k_init<<<(NN + 255) / 256, 256>>>();
    k_count<<<(EE + 255) / 256, 256>>>(ei, batch);
    k_dinv<<<(NN + 255) / 256, 256>>>();

    int gemm_blocks = (NN + 31) / 32;
    long long scat_threads = (long long)EE * 8;
    int scat_blocks = (int)((scat_threads + 255) / 256);

    k_gemm<<<gemm_blocks, 256>>>(x, W0, nullptr, 0);
    k_scatter<<<scat_blocks, 256>>>(ei);
    k_gemm<<<gemm_blocks, 256>>>(nullptr, W1, b0, 1);
    k_scatter<<<scat_blocks, 256>>>(ei);
    k_gemm<<<gemm_blocks, 256>>>(nullptr, W2, b1, 1);
    k_scatter<<<scat_blocks, 256>>>(ei);

    k_pool<<<(NN + 255) / 256, 256>>>(b2, Wp, batch);
    k_final<<<1, 64>>>(bp, out);
}

// round 2
// speedup vs baseline: 1.1555x; 1.1555x over previous
#include <cuda_runtime.h>

#define NN 50000
#define EE 1250000
#define HH 64
#define GG 64

// Scratch (device globals)
__device__ float    g_xa[NN*HH];    // xws ping
__device__ float    g_xb[NN*HH];    // xws pong
__device__ float    g_dinv[NN];
__device__ unsigned g_deg[NN];      // degree, then reused as CSR fill cursor
__device__ int      g_rowptr[NN+1];
__device__ int      g_srcl[EE];     // CSR: src node per edge, grouped by dst
__device__ float    g_cnt[GG];
__device__ float    g_sumP[GG];
__device__ int      g_idx64;

// ---------------------------------------------------------------------------
__global__ void k_detect(const int* batch_raw) {
    g_idx64 = (batch_raw[NN - 1] == 0) ? 1 : 0;
}

__global__ void k_init() {
    int i = blockIdx.x * blockDim.x + threadIdx.x;
    if (i < NN) g_deg[i] = 0u;
    if (i < GG) { g_cnt[i] = 0.f; g_sumP[i] = 0.f; }
}

__device__ __forceinline__ int load_idx(const void* p, long long i, int is64) {
    return is64 ? (int)((const long long*)p)[i] : ((const int*)p)[i];
}

// degree over dst + per-graph node counts
__global__ void k_count(const void* ei, const void* batch) {
    int i = blockIdx.x * blockDim.x + threadIdx.x;
    int is64 = g_idx64;
    if (i < EE) {
        int d = load_idx(ei, (long long)EE + i, is64);
        atomicAdd(&g_deg[d], 1u);
    }
    if (i < NN) {
        int b = load_idx(batch, i, is64);
        atomicAdd(&g_cnt[b], 1.0f);
    }
}

// Single-block scan: rowptr = exclusive_scan(deg); also dinv; reset deg->0.
__global__ __launch_bounds__(1024) void k_scan() {
    __shared__ int sm[1024];
    const int CH = 49;                       // 1024*49 >= 50000
    int t = threadIdx.x;
    int base = t * CH;
    int sum = 0;
    #pragma unroll 1
    for (int i = 0; i < CH; i++) {
        int idx = base + i;
        if (idx < NN) sum += (int)g_deg[idx];
    }
    sm[t] = sum;
    __syncthreads();
    for (int off = 1; off < 1024; off <<= 1) {
        int v = (t >= off) ? sm[t - off] : 0;
        __syncthreads();
        sm[t] += v;
        __syncthreads();
    }
    int run = (t > 0) ? sm[t - 1] : 0;
    #pragma unroll 1
    for (int i = 0; i < CH; i++) {
        int idx = base + i;
        if (idx < NN) {
            int d = (int)g_deg[idx];
            g_rowptr[idx] = run;
            run += d;
            g_dinv[idx] = rsqrtf((float)d + 1.0f);
            g_deg[idx] = 0u;                 // reuse as fill cursor
        }
    }
    if (t == 1023) g_rowptr[NN] = EE;
}

// Bucket edges by dst into CSR
__global__ void k_fill(const void* __restrict__ ei) {
    int i = blockIdx.x * blockDim.x + threadIdx.x;
    if (i >= EE) return;
    int is64 = g_idx64;
    int s = load_idx(ei, i, is64);
    int d = load_idx(ei, (long long)EE + i, is64);
    int slot = (int)atomicAdd(&g_deg[d], 1u);
    g_srcl[g_rowptr[d] + slot] = s;
}

// ---------------------------------------------------------------------------
// Warp-level CSR gather for one dst row: acc over incident src rows of X.
// lane covers cols (lane, lane+32).
__device__ __forceinline__ void gather_row(const float* __restrict__ X,
                                           int n, int lane,
                                           float& a0, float& a1)
{
    int e  = g_rowptr[n];
    int e1 = g_rowptr[n + 1];
    a0 = 0.f; a1 = 0.f;
    float b0 = 0.f, b1 = 0.f;   // second accumulator pair for ILP
    for (; e + 2 <= e1; e += 2) {
        int i0 = g_srcl[e], i1 = g_srcl[e + 1];
        const float* p0 = X + (long long)i0 * 64 + lane;
        const float* p1 = X + (long long)i1 * 64 + lane;
        float x0 = p0[0], y0 = p0[32];
        float x1 = p1[0], y1 = p1[32];
        a0 += x0; a1 += y0;
        b0 += x1; b1 += y1;
    }
    if (e < e1) {
        int i0 = g_srcl[e];
        const float* p0 = X + (long long)i0 * 64 + lane;
        a0 += p0[0]; a1 += p0[32];
    }
    a0 += b0; a1 += b1;
}

// ---------------------------------------------------------------------------
// Fused layer kernel. mode 0: input = raw x (row-major [N,64]).
// mode 1: input tile produced by warp-gather + epilogue relu(dinv*(agg+self)+b).
// Output: OUT = (h @ W) * dinv  (row-scaled for next gather).
__global__ __launch_bounds__(256) void k_gemm(const float* __restrict__ X,
                                              const float* __restrict__ INX,
                                              float* __restrict__ OUT,
                                              const float* __restrict__ W,
                                              const float* __restrict__ bprev,
                                              int mode)
{
    __shared__ float sWt[64][68];   // Wt[j][k] = W[k][j]
    __shared__ float sIn[32][68];

    int t = threadIdx.x;
    int row0 = blockIdx.x * 32;
    int wp = t >> 5, l = t & 31;

    // Load + transpose W
    #pragma unroll
    for (int p = 0; p < 4; p++) {
        int off = p * 1024 + t * 4;
        float4 w = *(const float4*)(W + off);
        int k = off >> 6;
        int j = off & 63;
        sWt[j+0][k] = w.x; sWt[j+1][k] = w.y; sWt[j+2][k] = w.z; sWt[j+3][k] = w.w;
    }

    if (mode == 0) {
        int rr = t >> 3;
        int c0 = (t & 7) * 8;
        int n  = row0 + rr;
        if (n < NN) {
            float4 a = *(const float4*)(X + (long long)n*64 + c0);
            float4 b = *(const float4*)(X + (long long)n*64 + c0 + 4);
            *(float4*)&sIn[rr][c0]   = a;
            *(float4*)&sIn[rr][c0+4] = b;
        } else {
            float4 z = make_float4(0.f,0.f,0.f,0.f);
            *(float4*)&sIn[rr][c0]   = z;
            *(float4*)&sIn[rr][c0+4] = z;
        }
    } else {
        // warp wp gathers rows row0+wp*4 .. +3
        float bb0 = bprev[l], bb1 = bprev[l + 32];
        #pragma unroll 1
        for (int r = 0; r < 4; r++) {
            int rr = wp * 4 + r;
            int n = row0 + rr;
            if (n < NN) {
                float a0, a1;
                gather_row(INX, n, l, a0, a1);
                float dv = g_dinv[n];
                float s0 = INX[(long long)n*64 + l];
                float s1 = INX[(long long)n*64 + l + 32];
                sIn[rr][l]      = fmaxf(fmaf(dv, a0 + s0, bb0), 0.f);
                sIn[rr][l + 32] = fmaxf(fmaf(dv, a1 + s1, bb1), 0.f);
            } else {
                sIn[rr][l] = 0.f; sIn[rr][l + 32] = 0.f;
            }
        }
    }
    __syncthreads();

    // Compute: warp wp -> rows wp*4..+3; lane l -> cols l, l+32
    int r0 = wp * 4;
    float acc[4][2] = {};
    #pragma unroll
    for (int k4 = 0; k4 < 64; k4 += 4) {
        float4 w0 = *(float4*)&sWt[l][k4];
        float4 w1 = *(float4*)&sWt[l + 32][k4];
        #pragma unroll
        for (int r = 0; r < 4; r++) {
            float4 a = *(float4*)&sIn[r0 + r][k4];
            acc[r][0] += a.x*w0.x + a.y*w0.y + a.z*w0.z + a.w*w0.w;
            acc[r][1] += a.x*w1.x + a.y*w1.y + a.z*w1.z + a.w*w1.w;
        }
    }

    #pragma unroll
    for (int r = 0; r < 4; r++) {
        int n2 = row0 + r0 + r;
        if (n2 < NN) {
            float dv = g_dinv[n2];
            OUT[(long long)n2*64 + l]      = acc[r][0] * dv;
            OUT[(long long)n2*64 + l + 32] = acc[r][1] * dv;
        }
    }
}

// ---------------------------------------------------------------------------
// Final layer: warp per node: gather + epilogue + dot(Wp) + per-graph sum.
__global__ __launch_bounds__(256) void k_pool(const float* __restrict__ INX,
                                              const float* __restrict__ b2,
                                              const float* __restrict__ Wp,
                                              const void* __restrict__ batch)
{
    int t = threadIdx.x;
    int wp = t >> 5, l = t & 31;
    int n = blockIdx.x * 8 + wp;
    if (n >= NN) return;

    float a0, a1;
    gather_row(INX, n, l, a0, a1);
    float dv = g_dinv[n];
    float s0 = INX[(long long)n*64 + l];
    float s1 = INX[(long long)n*64 + l + 32];
    float h0 = fmaf(dv, a0 + s0, b2[l]);
    float h1 = fmaf(dv, a1 + s1, b2[l + 32]);
    float p = h0 * Wp[l] + h1 * Wp[l + 32];

    // warp reduce
    #pragma unroll
    for (int off = 16; off > 0; off >>= 1)
        p += __shfl_xor_sync(0xffffffffu, p, off);

    if (l == 0) {
        int g = g_idx64 ? (int)((const long long*)batch)[n]
                        : ((const int*)batch)[n];
        atomicAdd(&g_sumP[g], p);
    }
}

__global__ void k_final(const float* __restrict__ bp, float* __restrict__ out) {
    int g = threadIdx.x;
    if (g < GG) out[g] = g_sumP[g] / fmaxf(g_cnt[g], 1.0f) + bp[0];
}

// ---------------------------------------------------------------------------
extern "C" void kernel_launch(void* const* d_in, const int* in_sizes, int n_in,
                              void* d_out, int out_size)
{
    const float* x     = (const float*)d_in[0];
    const void*  ei    = d_in[1];
    const void*  batch = d_in[2];
    const float* W0    = (const float*)d_in[3];
    const float* b0    = (const float*)d_in[4];
    const float* W1    = (const float*)d_in[5];
    const float* b1    = (const float*)d_in[6];
    const float* W2    = (const float*)d_in[7];
    const float* b2    = (const float*)d_in[8];
    const float* Wp    = (const float*)d_in[9];
    const float* bp    = (const float*)d_in[10];
    float* out = (float*)d_out;

    float* XA; cudaGetSymbolAddress((void**)&XA, g_xa);
    float* XB; cudaGetSymbolAddress((void**)&XB, g_xb);

    k_detect<<<1, 1>>>((const int*)batch);
    k_init<<<(NN + 255) / 256, 256>>>();
    k_count<<<(EE + 255) / 256, 256>>>(ei, batch);
    k_scan<<<1, 1024>>>();
    k_fill<<<(EE + 255) / 256, 256>>>(ei);

    int gemm_blocks = (NN + 31) / 32;
    // layer 0: x @ W0 -> XA (scaled)
    k_gemm<<<gemm_blocks, 256>>>(x, nullptr, XA, W0, nullptr, 0);
    // layer 1: gather(XA) -> h -> @W1 -> XB
    k_gemm<<<gemm_blocks, 256>>>(nullptr, XA, XB, W1, b0, 1);
    // layer 2: gather(XB) -> h -> @W2 -> XA
    k_gemm<<<gemm_blocks, 256>>>(nullptr, XB, XA, W2, b1, 1);
    // head: gather(XA) + b2, dot Wp, mean per graph
    k_pool<<<(NN + 7) / 8, 256>>>(XA, b2, Wp, batch);
    k_final<<<1, 64>>>(bp, out);
}

// round 5
// speedup vs baseline: 1.5813x; 1.3685x over previous
#include <cuda_runtime.h>

#define NN 50000
#define EE 1250000
#define HH 64
#define GG 64

#define SCAN_B 512
#define SCAN_NB ((NN + SCAN_B - 1) / SCAN_B)   // 98

// Scratch (device globals)
__device__ float    g_xa[NN*HH];
__device__ float    g_xb[NN*HH];
__device__ float    g_dinv[NN];
__device__ unsigned g_deg[NN];      // degree, then reused as CSR fill cursor
__device__ int      g_rowptr[NN+1];
__device__ int      g_srcl[EE];     // CSR: src node per edge, grouped by dst
__device__ int      g_bsum[SCAN_NB];
__device__ int      g_boff[SCAN_NB];
__device__ float    g_cnt[GG];
__device__ float    g_sumP[GG];
__device__ int      g_idx64;

// ---------------------------------------------------------------------------
__global__ void k_detect(const int* batch_raw) {
    g_idx64 = (batch_raw[NN - 1] == 0) ? 1 : 0;
}

__global__ void k_init() {
    int i = blockIdx.x * blockDim.x + threadIdx.x;
    if (i < NN) g_deg[i] = 0u;
    if (i < GG) { g_cnt[i] = 0.f; g_sumP[i] = 0.f; }
}

__device__ __forceinline__ int load_idx(const void* p, long long i, int is64) {
    return is64 ? (int)((const long long*)p)[i] : ((const int*)p)[i];
}

__global__ void k_count(const void* ei, const void* batch) {
    int i = blockIdx.x * blockDim.x + threadIdx.x;
    int is64 = g_idx64;
    if (i < EE) {
        int d = load_idx(ei, (long long)EE + i, is64);
        atomicAdd(&g_deg[d], 1u);
    }
    if (i < NN) {
        int b = load_idx(batch, i, is64);
        atomicAdd(&g_cnt[b], 1.0f);
    }
}

// ---------------------------------------------------------------------------
// Multi-block exclusive scan of g_deg -> g_rowptr (3 phases).
// Phase 1: per-block exclusive scan + block total; also dinv + deg reset.
__global__ __launch_bounds__(SCAN_B) void k_scan1() {
    __shared__ int sWarp[SCAN_B / 32];   // 16
    int t = threadIdx.x;
    int i = blockIdx.x * SCAN_B + t;
    int l = t & 31, w = t >> 5;

    int d = (i < NN) ? (int)g_deg[i] : 0;

    // warp inclusive scan (all lanes participate)
    int v = d;
    #pragma unroll
    for (int off = 1; off < 32; off <<= 1) {
        int u = __shfl_up_sync(0xffffffffu, v, off);
        if (l >= off) v += u;
    }
    if (l == 31) sWarp[w] = v;
    __syncthreads();
    if (w == 0) {                         // all 32 lanes of warp 0 enter
        int s = (l < SCAN_B / 32) ? sWarp[l] : 0;
        #pragma unroll
        for (int off = 1; off < SCAN_B / 32; off <<= 1) {
            int u = __shfl_up_sync(0xffffffffu, s, off);
            if (l >= off) s += u;
        }
        if (l < SCAN_B / 32) sWarp[l] = s;
    }
    __syncthreads();
    int excl = v - d + (w > 0 ? sWarp[w - 1] : 0);

    if (i < NN) {
        g_rowptr[i] = excl;               // local; offset added in phase 3
        g_dinv[i] = rsqrtf((float)d + 1.0f);
        g_deg[i] = 0u;                    // reuse as fill cursor
    }
    if (t == SCAN_B - 1) g_bsum[blockIdx.x] = excl + d;
}

// Phase 2: ONE WARP scans the 98 block sums. Each lane owns 4 consecutive
// entries (32*4 = 128 >= 98); serial scan within lane, shfl scan across lanes.
// Every shuffle is executed by all 32 lanes (guards on data only).
__global__ __launch_bounds__(32) void k_scan2() {
    int l = threadIdx.x;
    int v0 = (l*4+0 < SCAN_NB) ? g_bsum[l*4+0] : 0;
    int v1 = (l*4+1 < SCAN_NB) ? g_bsum[l*4+1] : 0;
    int v2 = (l*4+2 < SCAN_NB) ? g_bsum[l*4+2] : 0;
    int v3 = (l*4+3 < SCAN_NB) ? g_bsum[l*4+3] : 0;
    int lane_sum = v0 + v1 + v2 + v3;

    // inclusive scan of lane_sum across the warp
    int s = lane_sum;
    #pragma unroll
    for (int off = 1; off < 32; off <<= 1) {
        int u = __shfl_up_sync(0xffffffffu, s, off);
        if (l >= off) s += u;
    }
    int lane_excl = s - lane_sum;

    int r = lane_excl;
    if (l*4+0 < SCAN_NB) g_boff[l*4+0] = r; r += v0;
    if (l*4+1 < SCAN_NB) g_boff[l*4+1] = r; r += v1;
    if (l*4+2 < SCAN_NB) g_boff[l*4+2] = r; r += v2;
    if (l*4+3 < SCAN_NB) g_boff[l*4+3] = r;
}

// Phase 3: add block offsets.
__global__ __launch_bounds__(SCAN_B) void k_scan3() {
    int i = blockIdx.x * SCAN_B + threadIdx.x;
    if (i < NN) g_rowptr[i] += g_boff[blockIdx.x];
    if (i == 0) g_rowptr[NN] = EE;
}

// Bucket edges by dst into CSR
__global__ void k_fill(const void* __restrict__ ei) {
    int i = blockIdx.x * blockDim.x + threadIdx.x;
    if (i >= EE) return;
    int is64 = g_idx64;
    int s = load_idx(ei, i, is64);
    int d = load_idx(ei, (long long)EE + i, is64);
    int slot = (int)atomicAdd(&g_deg[d], 1u);
    g_srcl[g_rowptr[d] + slot] = s;
}

// ---------------------------------------------------------------------------
// Warp-level CSR gather for one dst row.
__device__ __forceinline__ void gather_row(const float* __restrict__ X,
                                           int n, int lane,
                                           float& a0, float& a1)
{
    int e  = g_rowptr[n];
    int e1 = g_rowptr[n + 1];
    a0 = 0.f; a1 = 0.f;
    float b0 = 0.f, b1 = 0.f;
    for (; e + 2 <= e1; e += 2) {
        int i0 = g_srcl[e], i1 = g_srcl[e + 1];
        const float* p0 = X + (long long)i0 * 64 + lane;
        const float* p1 = X + (long long)i1 * 64 + lane;
        float x0 = p0[0], y0 = p0[32];
        float x1 = p1[0], y1 = p1[32];
        a0 += x0; a1 += y0;
        b0 += x1; b1 += y1;
    }
    if (e < e1) {
        int i0 = g_srcl[e];
        const float* p0 = X + (long long)i0 * 64 + lane;
        a0 += p0[0]; a1 += p0[32];
    }
    a0 += b0; a1 += b1;
}

// ---------------------------------------------------------------------------
// Fused layer kernel. mode 0: input = raw x. mode 1: gather + epilogue.
__global__ __launch_bounds__(256) void k_gemm(const float* __restrict__ X,
                                              const float* __restrict__ INX,
                                              float* __restrict__ OUT,
                                              const float* __restrict__ W,
                                              const float* __restrict__ bprev,
                                              int mode)
{
    __shared__ float sWt[64][68];
    __shared__ float sIn[32][68];

    int t = threadIdx.x;
    int row0 = blockIdx.x * 32;
    int wp = t >> 5, l = t & 31;

    #pragma unroll
    for (int p = 0; p < 4; p++) {
        int off = p * 1024 + t * 4;
        float4 w = *(const float4*)(W + off);
        int k = off >> 6;
        int j = off & 63;
        sWt[j+0][k] = w.x; sWt[j+1][k] = w.y; sWt[j+2][k] = w.z; sWt[j+3][k] = w.w;
    }

    if (mode == 0) {
        int rr = t >> 3;
        int c0 = (t & 7) * 8;
        int n  = row0 + rr;
        if (n < NN) {
            float4 a = *(const float4*)(X + (long long)n*64 + c0);
            float4 b = *(const float4*)(X + (long long)n*64 + c0 + 4);
            *(float4*)&sIn[rr][c0]   = a;
            *(float4*)&sIn[rr][c0+4] = b;
        } else {
            float4 z = make_float4(0.f,0.f,0.f,0.f);
            *(float4*)&sIn[rr][c0]   = z;
            *(float4*)&sIn[rr][c0+4] = z;
        }
    } else {
        float bb0 = bprev[l], bb1 = bprev[l + 32];
        #pragma unroll 1
        for (int r = 0; r < 4; r++) {
            int rr = wp * 4 + r;
            int n = row0 + rr;
            if (n < NN) {
                float a0, a1;
                gather_row(INX, n, l, a0, a1);
                float dv = g_dinv[n];
                float s0 = INX[(long long)n*64 + l];
                float s1 = INX[(long long)n*64 + l + 32];
                sIn[rr][l]      = fmaxf(fmaf(dv, a0 + s0, bb0), 0.f);
                sIn[rr][l + 32] = fmaxf(fmaf(dv, a1 + s1, bb1), 0.f);
            } else {
                sIn[rr][l] = 0.f; sIn[rr][l + 32] = 0.f;
            }
        }
    }
    __syncthreads();

    int r0 = wp * 4;
    float acc[4][2] = {};
    #pragma unroll
    for (int k4 = 0; k4 < 64; k4 += 4) {
        float4 w0 = *(float4*)&sWt[l][k4];
        float4 w1 = *(float4*)&sWt[l + 32][k4];
        #pragma unroll
        for (int r = 0; r < 4; r++) {
            float4 a = *(float4*)&sIn[r0 + r][k4];
            acc[r][0] += a.x*w0.x + a.y*w0.y + a.z*w0.z + a.w*w0.w;
            acc[r][1] += a.x*w1.x + a.y*w1.y + a.z*w1.z + a.w*w1.w;
        }
    }

    #pragma unroll
    for (int r = 0; r < 4; r++) {
        int n2 = row0 + r0 + r;
        if (n2 < NN) {
            float dv = g_dinv[n2];
            OUT[(long long)n2*64 + l]      = acc[r][0] * dv;
            OUT[(long long)n2*64 + l + 32] = acc[r][1] * dv;
        }
    }
}

// ---------------------------------------------------------------------------
__global__ __launch_bounds__(256) void k_pool(const float* __restrict__ INX,
                                              const float* __restrict__ b2,
                                              const float* __restrict__ Wp,
                                              const void* __restrict__ batch)
{
    int t = threadIdx.x;
    int wp = t >> 5, l = t & 31;
    int n = blockIdx.x * 8 + wp;
    if (n >= NN) return;

    float a0, a1;
    gather_row(INX, n, l, a0, a1);
    float dv = g_dinv[n];
    float s0 = INX[(long long)n*64 + l];
    float s1 = INX[(long long)n*64 + l + 32];
    float h0 = fmaf(dv, a0 + s0, b2[l]);
    float h1 = fmaf(dv, a1 + s1, b2[l + 32]);
    float p = h0 * Wp[l] + h1 * Wp[l + 32];

    #pragma unroll
    for (int off = 16; off > 0; off >>= 1)
        p += __shfl_xor_sync(0xffffffffu, p, off);

    if (l == 0) {
        int g = g_idx64 ? (int)((const long long*)batch)[n]
                        : ((const int*)batch)[n];
        atomicAdd(&g_sumP[g], p);
    }
}

__global__ void k_final(const float* __restrict__ bp, float* __restrict__ out) {
    int g = threadIdx.x;
    if (g < GG) out[g] = g_sumP[g] / fmaxf(g_cnt[g], 1.0f) + bp[0];
}

// ---------------------------------------------------------------------------
extern "C" void kernel_launch(void* const* d_in, const int* in_sizes, int n_in,
                              void* d_out, int out_size)
{
    const float* x     = (const float*)d_in[0];
    const void*  ei    = d_in[1];
    const void*  batch = d_in[2];
    const float* W0    = (const float*)d_in[3];
    const float* b0    = (const float*)d_in[4];
    const float* W1    = (const float*)d_in[5];
    const float* b1    = (const float*)d_in[6];
    const float* W2    = (const float*)d_in[7];
    const float* b2    = (const float*)d_in[8];
    const float* Wp    = (const float*)d_in[9];
    const float* bp    = (const float*)d_in[10];
    float* out = (float*)d_out;

    float* XA; cudaGetSymbolAddress((void**)&XA, g_xa);
    float* XB; cudaGetSymbolAddress((void**)&XB, g_xb);

    k_detect<<<1, 1>>>((const int*)batch);
    k_init<<<(NN + 255) / 256, 256>>>();
    k_count<<<(EE + 255) / 256, 256>>>(ei, batch);
    k_scan1<<<SCAN_NB, SCAN_B>>>();
    k_scan2<<<1, 32>>>();
    k_scan3<<<SCAN_NB, SCAN_B>>>();
    k_fill<<<(EE + 255) / 256, 256>>>(ei);

    int gemm_blocks = (NN + 31) / 32;
    k_gemm<<<gemm_blocks, 256>>>(x, nullptr, XA, W0, nullptr, 0);
    k_gemm<<<gemm_blocks, 256>>>(nullptr, XA, XB, W1, b0, 1);
    k_gemm<<<gemm_blocks, 256>>>(nullptr, XB, XA, W2, b1, 1);
    k_pool<<<(NN + 7) / 8, 256>>>(XA, b2, Wp, batch);
    k_final<<<1, 64>>>(bp, out);
}

// round 7
// speedup vs baseline: 1.6124x; 1.0197x over previous
#include <cuda_runtime.h>
#include <cuda_fp16.h>

#define NN 50000
#define EE 1250000
#define HH 64
#define GG 64

#define SCAN_B 512
#define SCAN_NB ((NN + SCAN_B - 1) / SCAN_B)   // 98

// Scratch (device globals)
__device__ __half   g_xa[NN*HH];    // fp16 scaled features ping
__device__ __half   g_xb[NN*HH];    // fp16 scaled features pong
__device__ float    g_dinv[NN];
__device__ unsigned g_deg[NN];      // degree, then CSR fill cursor
__device__ int      g_rowptr[NN+1];
__device__ int      g_srcl[EE];
__device__ int      g_bsum[SCAN_NB];
__device__ int      g_boff[SCAN_NB];
__device__ float    g_cnt[GG];
__device__ float    g_sumP[GG];
__device__ int      g_idx64;

// ---------------------------------------------------------------------------
__global__ void k_detect(const int* batch_raw) {
    g_idx64 = (batch_raw[NN - 1] == 0) ? 1 : 0;
}

__global__ void k_init() {
    int i = blockIdx.x * blockDim.x + threadIdx.x;
    if (i < NN) g_deg[i] = 0u;
    if (i < GG) { g_cnt[i] = 0.f; g_sumP[i] = 0.f; }
}

__device__ __forceinline__ int load_idx(const void* p, long long i, int is64) {
    return is64 ? (int)((const long long*)p)[i] : ((const int*)p)[i];
}

__global__ void k_count(const void* ei, const void* batch) {
    int i = blockIdx.x * blockDim.x + threadIdx.x;
    int is64 = g_idx64;
    if (i < EE) {
        int d = load_idx(ei, (long long)EE + i, is64);
        atomicAdd(&g_deg[d], 1u);
    }
    if (i < NN) {
        int b = load_idx(batch, i, is64);
        atomicAdd(&g_cnt[b], 1.0f);
    }
}

// ---------------------------------------------------------------------------
// 3-phase exclusive scan of g_deg -> g_rowptr.
__global__ __launch_bounds__(SCAN_B) void k_scan1() {
    __shared__ int sWarp[SCAN_B / 32];
    int t = threadIdx.x;
    int i = blockIdx.x * SCAN_B + t;
    int l = t & 31, w = t >> 5;

    int d = (i < NN) ? (int)g_deg[i] : 0;

    int v = d;
    #pragma unroll
    for (int off = 1; off < 32; off <<= 1) {
        int u = __shfl_up_sync(0xffffffffu, v, off);
        if (l >= off) v += u;
    }
    if (l == 31) sWarp[w] = v;
    __syncthreads();
    if (w == 0) {
        int s = (l < SCAN_B / 32) ? sWarp[l] : 0;
        #pragma unroll
        for (int off = 1; off < SCAN_B / 32; off <<= 1) {
            int u = __shfl_up_sync(0xffffffffu, s, off);
            if (l >= off) s += u;
        }
        if (l < SCAN_B / 32) sWarp[l] = s;
    }
    __syncthreads();
    int excl = v - d + (w > 0 ? sWarp[w - 1] : 0);

    if (i < NN) {
        g_rowptr[i] = excl;
        g_dinv[i] = rsqrtf((float)d + 1.0f);
        g_deg[i] = 0u;
    }
    if (t == SCAN_B - 1) g_bsum[blockIdx.x] = excl + d;
}

__global__ __launch_bounds__(32) void k_scan2() {
    int l = threadIdx.x;
    int v0 = (l*4+0 < SCAN_NB) ? g_bsum[l*4+0] : 0;
    int v1 = (l*4+1 < SCAN_NB) ? g_bsum[l*4+1] : 0;
    int v2 = (l*4+2 < SCAN_NB) ? g_bsum[l*4+2] : 0;
    int v3 = (l*4+3 < SCAN_NB) ? g_bsum[l*4+3] : 0;
    int lane_sum = v0 + v1 + v2 + v3;

    int s = lane_sum;
    #pragma unroll
    for (int off = 1; off < 32; off <<= 1) {
        int u = __shfl_up_sync(0xffffffffu, s, off);
        if (l >= off) s += u;
    }
    int r = s - lane_sum;
    if (l*4+0 < SCAN_NB) g_boff[l*4+0] = r; r += v0;
    if (l*4+1 < SCAN_NB) g_boff[l*4+1] = r; r += v1;
    if (l*4+2 < SCAN_NB) g_boff[l*4+2] = r; r += v2;
    if (l*4+3 < SCAN_NB) g_boff[l*4+3] = r;
}

__global__ __launch_bounds__(SCAN_B) void k_scan3() {
    int i = blockIdx.x * SCAN_B + threadIdx.x;
    if (i < NN) g_rowptr[i] += g_boff[blockIdx.x];
    if (i == 0) g_rowptr[NN] = EE;
}

__global__ void k_fill(const void* __restrict__ ei) {
    int i = blockIdx.x * blockDim.x + threadIdx.x;
    if (i >= EE) return;
    int is64 = g_idx64;
    int s = load_idx(ei, i, is64);
    int d = load_idx(ei, (long long)EE + i, is64);
    int slot = (int)atomicAdd(&g_deg[d], 1u);
    g_srcl[g_rowptr[d] + slot] = s;
}

// ---------------------------------------------------------------------------
// Warp CSR gather (fp16 rows): lane covers cols (2l, 2l+1) via one half2 load
// per edge. fp32 accumulation, 4-deep ILP.
__device__ __forceinline__ void gather_row_h(const __half2* __restrict__ X2,
                                             int n, int lane,
                                             float& a0, float& a1)
{
    int e  = g_rowptr[n];
    int e1 = g_rowptr[n + 1];
    float p0 = 0.f, p1 = 0.f, q0 = 0.f, q1 = 0.f;
    float r0 = 0.f, r1 = 0.f, s0 = 0.f, s1 = 0.f;
    for (; e + 4 <= e1; e += 4) {
        int i0 = g_srcl[e], i1 = g_srcl[e+1], i2 = g_srcl[e+2], i3 = g_srcl[e+3];
        float2 f0 = __half22float2(X2[i0 * 32 + lane]);
        float2 f1 = __half22float2(X2[i1 * 32 + lane]);
        float2 f2 = __half22float2(X2[i2 * 32 + lane]);
        float2 f3 = __half22float2(X2[i3 * 32 + lane]);
        p0 += f0.x; p1 += f0.y;
        q0 += f1.x; q1 += f1.y;
        r0 += f2.x; r1 += f2.y;
        s0 += f3.x; s1 += f3.y;
    }
    for (; e < e1; e++) {
        int i0 = g_srcl[e];
        float2 f0 = __half22float2(X2[i0 * 32 + lane]);
        p0 += f0.x; p1 += f0.y;
    }
    a0 = (p0 + q0) + (r0 + s0);
    a1 = (p1 + q1) + (r1 + s1);
}

// ---------------------------------------------------------------------------
// Fused layer. mode 0: input = raw fp32 x. mode 1: warp-gather fp16 + epilogue
// relu(dinv*(agg+self)+b). Output: fp16 (h@W)*dinv.
__global__ __launch_bounds__(256) void k_gemm(const float* __restrict__ X,
                                              const __half* __restrict__ INH,
                                              __half* __restrict__ OUT,
                                              const float* __restrict__ W,
                                              const float* __restrict__ bprev,
                                              int mode)
{
    __shared__ float sWt[64][68];
    __shared__ float sIn[32][68];

    int t = threadIdx.x;
    int row0 = blockIdx.x * 32;
    int wp = t >> 5, l = t & 31;

    #pragma unroll
    for (int p = 0; p < 4; p++) {
        int off = p * 1024 + t * 4;
        float4 w = *(const float4*)(W + off);
        int k = off >> 6;
        int j = off & 63;
        sWt[j+0][k] = w.x; sWt[j+1][k] = w.y; sWt[j+2][k] = w.z; sWt[j+3][k] = w.w;
    }

    if (mode == 0) {
        int rr = t >> 3;
        int c0 = (t & 7) * 8;
        int n  = row0 + rr;
        if (n < NN) {
            float4 a = *(const float4*)(X + (long long)n*64 + c0);
            float4 b = *(const float4*)(X + (long long)n*64 + c0 + 4);
            *(float4*)&sIn[rr][c0]   = a;
            *(float4*)&sIn[rr][c0+4] = b;
        } else {
            float4 z = make_float4(0.f,0.f,0.f,0.f);
            *(float4*)&sIn[rr][c0]   = z;
            *(float4*)&sIn[rr][c0+4] = z;
        }
    } else {
        const __half2* IN2 = (const __half2*)INH;
        float bb0 = bprev[2*l], bb1 = bprev[2*l + 1];
        #pragma unroll 1
        for (int r = 0; r < 4; r++) {
            int rr = wp * 4 + r;
            int n = row0 + rr;
            if (n < NN) {
                float a0, a1;
                gather_row_h(IN2, n, l, a0, a1);
                float dv = g_dinv[n];
                float2 sf = __half22float2(IN2[n * 32 + l]);
                sIn[rr][2*l]     = fmaxf(fmaf(dv, a0 + sf.x, bb0), 0.f);
                sIn[rr][2*l + 1] = fmaxf(fmaf(dv, a1 + sf.y, bb1), 0.f);
            } else {
                sIn[rr][2*l] = 0.f; sIn[rr][2*l + 1] = 0.f;
            }
        }
    }
    __syncthreads();

    // Compute: warp wp -> rows wp*4..+3; lane l -> cols l, l+32
    int r0 = wp * 4;
    float acc[4][2] = {};
    #pragma unroll
    for (int k4 = 0; k4 < 64; k4 += 4) {
        float4 w0 = *(float4*)&sWt[l][k4];
        float4 w1 = *(float4*)&sWt[l + 32][k4];
        #pragma unroll
        for (int r = 0; r < 4; r++) {
            float4 a = *(float4*)&sIn[r0 + r][k4];
            acc[r][0] += a.x*w0.x + a.y*w0.y + a.z*w0.z + a.w*w0.w;
            acc[r][1] += a.x*w1.x + a.y*w1.y + a.z*w1.z + a.w*w1.w;
        }
    }

    #pragma unroll
    for (int r = 0; r < 4; r++) {
        int n2 = row0 + r0 + r;
        if (n2 < NN) {
            float dv = g_dinv[n2];
            OUT[(long long)n2*64 + l]      = __float2half_rn(acc[r][0] * dv);
            OUT[(long long)n2*64 + l + 32] = __float2half_rn(acc[r][1] * dv);
        }
    }
}

// ---------------------------------------------------------------------------
__global__ __launch_bounds__(256) void k_pool(const __half* __restrict__ INH,
                                              const float* __restrict__ b2,
                                              const float* __restrict__ Wp,
                                              const void* __restrict__ batch)
{
    int t = threadIdx.x;
    int wp = t >> 5, l = t & 31;
    int n = blockIdx.x * 8 + wp;
    if (n >= NN) return;

    const __half2* IN2 = (const __half2*)INH;
    float a0, a1;
    gather_row_h(IN2, n, l, a0, a1);
    float dv = g_dinv[n];
    float2 sf = __half22float2(IN2[n * 32 + l]);
    float h0 = fmaf(dv, a0 + sf.x, b2[2*l]);
    float h1 = fmaf(dv, a1 + sf.y, b2[2*l + 1]);
    float p = h0 * Wp[2*l] + h1 * Wp[2*l + 1];

    #pragma unroll
    for (int off = 16; off > 0; off >>= 1)
        p += __shfl_xor_sync(0xffffffffu, p, off);

    if (l == 0) {
        int g = g_idx64 ? (int)((const long long*)batch)[n]
                        : ((const int*)batch)[n];
        atomicAdd(&g_sumP[g], p);
    }
}

__global__ void k_final(const float* __restrict__ bp, float* __restrict__ out) {
    int g = threadIdx.x;
    if (g < GG) out[g] = g_sumP[g] / fmaxf(g_cnt[g], 1.0f) + bp[0];
}

// ---------------------------------------------------------------------------
extern "C" void kernel_launch(void* const* d_in, const int* in_sizes, int n_in,
                              void* d_out, int out_size)
{
    const float* x     = (const float*)d_in[0];
    const void*  ei    = d_in[1];
    const void*  batch = d_in[2];
    const float* W0    = (const float*)d_in[3];
    const float* b0    = (const float*)d_in[4];
    const float* W1    = (const float*)d_in[5];
    const float* b1    = (const float*)d_in[6];
    const float* W2    = (const float*)d_in[7];
    const float* b2    = (const float*)d_in[8];
    const float* Wp    = (const float*)d_in[9];
    const float* bp    = (const float*)d_in[10];
    float* out = (float*)d_out;

    __half* XA; cudaGetSymbolAddress((void**)&XA, g_xa);
    __half* XB; cudaGetSymbolAddress((void**)&XB, g_xb);

    k_detect<<<1, 1>>>((const int*)batch);
    k_init<<<(NN + 255) / 256, 256>>>();
    k_count<<<(EE + 255) / 256, 256>>>(ei, batch);
    k_scan1<<<SCAN_NB, SCAN_B>>>();
    k_scan2<<<1, 32>>>();
    k_scan3<<<SCAN_NB, SCAN_B>>>();
    k_fill<<<(EE + 255) / 256, 256>>>(ei);

    int gemm_blocks = (NN + 31) / 32;
    k_gemm<<<gemm_blocks, 256>>>(x, nullptr, XA, W0, nullptr, 0);
    k_gemm<<<gemm_blocks, 256>>>(nullptr, XA, XB, W1, b0, 1);
    k_gemm<<<gemm_blocks, 256>>>(nullptr, XB, XA, W2, b1, 1);
    k_pool<<<(NN + 7) / 8, 256>>>(XA, b2, Wp, batch);
    k_final<<<1, 64>>>(bp, out);
}

// round 8
// speedup vs baseline: 1.8649x; 1.1566x over previous
#include <cuda_runtime.h>
#include <cuda_fp16.h>

#define NN 50000
#define EE 1250000
#define HH 64
#define GG 64

#define SCAN_B 512
#define SCAN_NB ((NN + SCAN_B - 1) / SCAN_B)   // 98

// Scratch (device globals)
__device__ __half   g_xa[NN*HH];    // fp16 scaled features ping
__device__ __half   g_xb[NN*HH];    // fp16 scaled features pong
__device__ float    g_z[NN];        // per-node scalar z = (h2 . wv) * dinv
__device__ float    g_dinv[NN];
__device__ unsigned g_deg[NN];
__device__ int      g_rowptr[NN+1];
__device__ int      g_srcl[EE];
__device__ int      g_bsum[SCAN_NB];
__device__ int      g_boff[SCAN_NB];
__device__ float    g_cnt[GG];
__device__ float    g_sumP[GG];
__device__ float    g_wv[HH];       // W2 @ Wp
__device__ float    g_c;            // b2 . Wp
__device__ int      g_idx64;

// ---------------------------------------------------------------------------
// init: zero deg/cnt/sumP, detect index width, compute wv = W2@Wp, c = b2.Wp
__global__ void k_init(const int* batch_raw, const float* __restrict__ W2,
                       const float* __restrict__ b2, const float* __restrict__ Wp) {
    int i = blockIdx.x * blockDim.x + threadIdx.x;
    if (i < NN) g_deg[i] = 0u;
    if (i < GG) { g_cnt[i] = 0.f; g_sumP[i] = 0.f; }
    if (blockIdx.x == 0) {
        int t = threadIdx.x;
        if (t == 255) g_idx64 = (batch_raw[NN - 1] == 0) ? 1 : 0;
        if (t < 64) {
            float s = 0.f;
            #pragma unroll
            for (int j = 0; j < 64; j++) s += W2[t * 64 + j] * Wp[j];
            g_wv[t] = s;
        }
        if (t == 64) {
            float s = 0.f;
            for (int j = 0; j < 64; j++) s += b2[j] * Wp[j];
            g_c = s;
        }
    }
}

__device__ __forceinline__ int load_idx(const void* p, long long i, int is64) {
    return is64 ? (int)((const long long*)p)[i] : ((const int*)p)[i];
}

__global__ void k_count(const void* ei, const void* batch) {
    int i = blockIdx.x * blockDim.x + threadIdx.x;
    int is64 = g_idx64;
    if (i < EE) {
        int d = load_idx(ei, (long long)EE + i, is64);
        atomicAdd(&g_deg[d], 1u);
    }
    if (i < NN) {
        int b = load_idx(batch, i, is64);
        atomicAdd(&g_cnt[b], 1.0f);
    }
}

// ---------------------------------------------------------------------------
// 3-phase exclusive scan of g_deg -> g_rowptr.
__global__ __launch_bounds__(SCAN_B) void k_scan1() {
    __shared__ int sWarp[SCAN_B / 32];
    int t = threadIdx.x;
    int i = blockIdx.x * SCAN_B + t;
    int l = t & 31, w = t >> 5;

    int d = (i < NN) ? (int)g_deg[i] : 0;

    int v = d;
    #pragma unroll
    for (int off = 1; off < 32; off <<= 1) {
        int u = __shfl_up_sync(0xffffffffu, v, off);
        if (l >= off) v += u;
    }
    if (l == 31) sWarp[w] = v;
    __syncthreads();
    if (w == 0) {
        int s = (l < SCAN_B / 32) ? sWarp[l] : 0;
        #pragma unroll
        for (int off = 1; off < SCAN_B / 32; off <<= 1) {
            int u = __shfl_up_sync(0xffffffffu, s, off);
            if (l >= off) s += u;
        }
        if (l < SCAN_B / 32) sWarp[l] = s;
    }
    __syncthreads();
    int excl = v - d + (w > 0 ? sWarp[w - 1] : 0);

    if (i < NN) {
        g_rowptr[i] = excl;
        g_dinv[i] = rsqrtf((float)d + 1.0f);
        g_deg[i] = 0u;
    }
    if (t == SCAN_B - 1) g_bsum[blockIdx.x] = excl + d;
}

__global__ __launch_bounds__(32) void k_scan2() {
    int l = threadIdx.x;
    int v0 = (l*4+0 < SCAN_NB) ? g_bsum[l*4+0] : 0;
    int v1 = (l*4+1 < SCAN_NB) ? g_bsum[l*4+1] : 0;
    int v2 = (l*4+2 < SCAN_NB) ? g_bsum[l*4+2] : 0;
    int v3 = (l*4+3 < SCAN_NB) ? g_bsum[l*4+3] : 0;
    int lane_sum = v0 + v1 + v2 + v3;

    int s = lane_sum;
    #pragma unroll
    for (int off = 1; off < 32; off <<= 1) {
        int u = __shfl_up_sync(0xffffffffu, s, off);
        if (l >= off) s += u;
    }
    int r = s - lane_sum;
    if (l*4+0 < SCAN_NB) g_boff[l*4+0] = r; r += v0;
    if (l*4+1 < SCAN_NB) g_boff[l*4+1] = r; r += v1;
    if (l*4+2 < SCAN_NB) g_boff[l*4+2] = r; r += v2;
    if (l*4+3 < SCAN_NB) g_boff[l*4+3] = r;
}

__global__ __launch_bounds__(SCAN_B) void k_scan3() {
    int i = blockIdx.x * SCAN_B + threadIdx.x;
    if (i < NN) g_rowptr[i] += g_boff[blockIdx.x];
    if (i == 0) g_rowptr[NN] = EE;
}

__global__ void k_fill(const void* __restrict__ ei) {
    int i = blockIdx.x * blockDim.x + threadIdx.x;
    if (i >= EE) return;
    int is64 = g_idx64;
    int s = load_idx(ei, i, is64);
    int d = load_idx(ei, (long long)EE + i, is64);
    int slot = (int)atomicAdd(&g_deg[d], 1u);
    g_srcl[g_rowptr[d] + slot] = s;
}

// ---------------------------------------------------------------------------
// Warp CSR gather (fp16 rows): lane covers cols (2l, 2l+1), fp32 accum, 4x ILP.
__device__ __forceinline__ void gather_row_h(const __half2* __restrict__ X2,
                                             int n, int lane,
                                             float& a0, float& a1)
{
    int e  = g_rowptr[n];
    int e1 = g_rowptr[n + 1];
    float p0 = 0.f, p1 = 0.f, q0 = 0.f, q1 = 0.f;
    float r0 = 0.f, r1 = 0.f, s0 = 0.f, s1 = 0.f;
    for (; e + 4 <= e1; e += 4) {
        int i0 = g_srcl[e], i1 = g_srcl[e+1], i2 = g_srcl[e+2], i3 = g_srcl[e+3];
        float2 f0 = __half22float2(X2[i0 * 32 + lane]);
        float2 f1 = __half22float2(X2[i1 * 32 + lane]);
        float2 f2 = __half22float2(X2[i2 * 32 + lane]);
        float2 f3 = __half22float2(X2[i3 * 32 + lane]);
        p0 += f0.x; p1 += f0.y;
        q0 += f1.x; q1 += f1.y;
        r0 += f2.x; r1 += f2.y;
        s0 += f3.x; s1 += f3.y;
    }
    for (; e < e1; e++) {
        int i0 = g_srcl[e];
        float2 f0 = __half22float2(X2[i0 * 32 + lane]);
        p0 += f0.x; p1 += f0.y;
    }
    a0 = (p0 + q0) + (r0 + s0);
    a1 = (p1 + q1) + (r1 + s1);
}

// ---------------------------------------------------------------------------
// Fused layer. mode 0: input = raw fp32 x. mode 1: warp-gather fp16 + epilogue.
__global__ __launch_bounds__(256) void k_gemm(const float* __restrict__ X,
                                              const __half* __restrict__ INH,
                                              __half* __restrict__ OUT,
                                              const float* __restrict__ W,
                                              const float* __restrict__ bprev,
                                              int mode)
{
    __shared__ float sWt[64][68];
    __shared__ float sIn[32][68];

    int t = threadIdx.x;
    int row0 = blockIdx.x * 32;
    int wp = t >> 5, l = t & 31;

    #pragma unroll
    for (int p = 0; p < 4; p++) {
        int off = p * 1024 + t * 4;
        float4 w = *(const float4*)(W + off);
        int k = off >> 6;
        int j = off & 63;
        sWt[j+0][k] = w.x; sWt[j+1][k] = w.y; sWt[j+2][k] = w.z; sWt[j+3][k] = w.w;
    }

    if (mode == 0) {
        int rr = t >> 3;
        int c0 = (t & 7) * 8;
        int n  = row0 + rr;
        if (n < NN) {
            float4 a = *(const float4*)(X + (long long)n*64 + c0);
            float4 b = *(const float4*)(X + (long long)n*64 + c0 + 4);
            *(float4*)&sIn[rr][c0]   = a;
            *(float4*)&sIn[rr][c0+4] = b;
        } else {
            float4 z = make_float4(0.f,0.f,0.f,0.f);
            *(float4*)&sIn[rr][c0]   = z;
            *(float4*)&sIn[rr][c0+4] = z;
        }
    } else {
        const __half2* IN2 = (const __half2*)INH;
        float bb0 = bprev[2*l], bb1 = bprev[2*l + 1];
        #pragma unroll 1
        for (int r = 0; r < 4; r++) {
            int rr = wp * 4 + r;
            int n = row0 + rr;
            if (n < NN) {
                float a0, a1;
                gather_row_h(IN2, n, l, a0, a1);
                float dv = g_dinv[n];
                float2 sf = __half22float2(IN2[n * 32 + l]);
                sIn[rr][2*l]     = fmaxf(fmaf(dv, a0 + sf.x, bb0), 0.f);
                sIn[rr][2*l + 1] = fmaxf(fmaf(dv, a1 + sf.y, bb1), 0.f);
            } else {
                sIn[rr][2*l] = 0.f; sIn[rr][2*l + 1] = 0.f;
            }
        }
    }
    __syncthreads();

    int r0 = wp * 4;
    float acc[4][2] = {};
    #pragma unroll
    for (int k4 = 0; k4 < 64; k4 += 4) {
        float4 w0 = *(float4*)&sWt[l][k4];
        float4 w1 = *(float4*)&sWt[l + 32][k4];
        #pragma unroll
        for (int r = 0; r < 4; r++) {
            float4 a = *(float4*)&sIn[r0 + r][k4];
            acc[r][0] += a.x*w0.x + a.y*w0.y + a.z*w0.z + a.w*w0.w;
            acc[r][1] += a.x*w1.x + a.y*w1.y + a.z*w1.z + a.w*w1.w;
        }
    }

    #pragma unroll
    for (int r = 0; r < 4; r++) {
        int n2 = row0 + r0 + r;
        if (n2 < NN) {
            float dv = g_dinv[n2];
            OUT[(long long)n2*64 + l]      = __float2half_rn(acc[r][0] * dv);
            OUT[(long long)n2*64 + l + 32] = __float2half_rn(acc[r][1] * dv);
        }
    }
}

// ---------------------------------------------------------------------------
// Layer-2 collapsed to per-node scalar: z_n = relu-epilogue(h2_n) . wv * dinv_n
__global__ __launch_bounds__(256) void k_z(const __half* __restrict__ INH,
                                           const float* __restrict__ b1)
{
    int t = threadIdx.x;
    int wp = t >> 5, l = t & 31;
    int n = blockIdx.x * 8 + wp;
    if (n >= NN) return;

    const __half2* IN2 = (const __half2*)INH;
    float a0, a1;
    gather_row_h(IN2, n, l, a0, a1);
    float dv = g_dinv[n];
    float2 sf = __half22float2(IN2[n * 32 + l]);
    float h0 = fmaxf(fmaf(dv, a0 + sf.x, b1[2*l]), 0.f);
    float h1 = fmaxf(fmaf(dv, a1 + sf.y, b1[2*l + 1]), 0.f);
    float p = h0 * g_wv[2*l] + h1 * g_wv[2*l + 1];

    #pragma unroll
    for (int off = 16; off > 0; off >>= 1)
        p += __shfl_xor_sync(0xffffffffu, p, off);

    if (l == 0) g_z[n] = p * dv;
}

// ---------------------------------------------------------------------------
// Scalar pool: p_n = dinv_n * (sum_src z_src + z_n) + c ; per-graph sums.
__global__ __launch_bounds__(256) void k_poolz(const void* __restrict__ batch)
{
    int t = threadIdx.x;
    int wp = t >> 5, l = t & 31;
    int n = blockIdx.x * 8 + wp;
    if (n >= NN) return;

    int e0 = g_rowptr[n];
    int e1 = g_rowptr[n + 1];
    float s = 0.f;
    for (int e = e0 + l; e < e1; e += 32)
        s += g_z[g_srcl[e]];

    #pragma unroll
    for (int off = 16; off > 0; off >>= 1)
        s += __shfl_xor_sync(0xffffffffu, s, off);

    if (l == 0) {
        float p = g_dinv[n] * (s + g_z[n]) + g_c;
        int g = g_idx64 ? (int)((const long long*)batch)[n]
                        : ((const int*)batch)[n];
        atomicAdd(&g_sumP[g], p);
    }
}

__global__ void k_final(const float* __restrict__ bp, float* __restrict__ out) {
    int g = threadIdx.x;
    if (g < GG) out[g] = g_sumP[g] / fmaxf(g_cnt[g], 1.0f) + bp[0];
}

// ---------------------------------------------------------------------------
extern "C" void kernel_launch(void* const* d_in, const int* in_sizes, int n_in,
                              void* d_out, int out_size)
{
    const float* x     = (const float*)d_in[0];
    const void*  ei    = d_in[1];
    const void*  batch = d_in[2];
    const float* W0    = (const float*)d_in[3];
    const float* b0    = (const float*)d_in[4];
    const float* W1    = (const float*)d_in[5];
    const float* b1    = (const float*)d_in[6];
    const float* W2    = (const float*)d_in[7];
    const float* b2    = (const float*)d_in[8];
    const float* Wp    = (const float*)d_in[9];
    const float* bp    = (const float*)d_in[10];
    float* out = (float*)d_out;

    __half* XA; cudaGetSymbolAddress((void**)&XA, g_xa);
    __half* XB; cudaGetSymbolAddress((void**)&XB, g_xb);

    k_init<<<(NN + 255) / 256, 256>>>((const int*)batch, W2, b2, Wp);
    k_count<<<(EE + 255) / 256, 256>>>(ei, batch);
    k_scan1<<<SCAN_NB, SCAN_B>>>();
    k_scan2<<<1, 32>>>();
    k_scan3<<<SCAN_NB, SCAN_B>>>();
    k_fill<<<(EE + 255) / 256, 256>>>(ei);

    int gemm_blocks = (NN + 31) / 32;
    // layer 0: x @ W0 -> XA (fp16, scaled)
    k_gemm<<<gemm_blocks, 256>>>(x, nullptr, XA, W0, nullptr, 0);
    // layer 1: gather(XA)+b0 -> h1 -> @W1 -> XB
    k_gemm<<<gemm_blocks, 256>>>(nullptr, XA, XB, W1, b0, 1);
    // layer 2 collapsed: z_n = (relu(dinv*(agg(XB)+self)+b1) . wv) * dinv
    k_z<<<(NN + 7) / 8, 256>>>(XB, b1);
    // scalar pool + head
    k_poolz<<<(NN + 7) / 8, 256>>>(batch);
    k_final<<<1, 64>>>(bp, out);
}